// round 1
// baseline (speedup 1.0000x reference)
#include <cuda_runtime.h>
#include <stdint.h>

#define NBINS    4096
#define CAND_CAP 8192
#define MAXN     524288
#define KSEL     64

// Scratch (no allocations allowed; __device__ globals per rules)
__device__ uint32_t            g_keys[MAXN];
__device__ uint32_t            g_hist[NBINS];
__device__ int                 g_threshBin;
__device__ int                 g_count;
__device__ unsigned long long  g_cand[CAND_CAP];

// Monotone float -> uint32 mapping (order-preserving incl. negatives)
__device__ __forceinline__ uint32_t f2key(float f) {
    uint32_t u = __float_as_uint(f);
    return (u & 0x80000000u) ? ~u : (u | 0x80000000u);
}

// K0: zero histogram + candidate counter (must re-zero every graph replay)
__global__ void k_zero() {
    int t = blockIdx.x * blockDim.x + threadIdx.x;
    if (t < NBINS) g_hist[t] = 0u;
    if (t == 0)    g_count   = 0;
}

// K1: warp-per-row dot product, write sortable key, fused shared-mem histogram
__global__ void k_score(const float4* __restrict__ q,
                        const float4* __restrict__ mat, int N) {
    __shared__ uint32_t sh[NBINS];
    for (int i = threadIdx.x; i < NBINS; i += blockDim.x) sh[i] = 0u;
    __syncthreads();

    const int lane   = threadIdx.x & 31;
    const int warp   = (blockIdx.x * blockDim.x + threadIdx.x) >> 5;
    const int nwarps = (gridDim.x * blockDim.x) >> 5;

    // Query fragment: 8 floats per lane (cols lane*4.. and 128+lane*4..)
    const float4 qa = q[lane];
    const float4 qb = q[lane + 32];

    for (int r = warp; r < N; r += nwarps) {
        const float4* row = mat + (size_t)r * 64;   // 256 floats = 64 float4
        float4 a = row[lane];
        float4 b = row[lane + 32];
        float s = a.x*qa.x + a.y*qa.y + a.z*qa.z + a.w*qa.w
                + b.x*qb.x + b.y*qb.y + b.z*qb.z + b.w*qb.w;
        #pragma unroll
        for (int o = 16; o; o >>= 1) s += __shfl_down_sync(0xffffffffu, s, o);
        if (lane == 0) {
            uint32_t key = f2key(s);
            g_keys[r] = key;
            atomicAdd(&sh[key >> 20], 1u);
        }
    }
    __syncthreads();
    for (int i = threadIdx.x; i < NBINS; i += blockDim.x) {
        uint32_t c = sh[i];
        if (c) atomicAdd(&g_hist[i], c);
    }
}

// K2: find threshold bin B (bin containing the K-th largest score).
// Coarse (64 blocks of 64 bins) then fine scan — ~128 serial iters total.
__global__ void k_thresh(int K) {
    __shared__ uint32_t coarse[64];
    int t = threadIdx.x;
    if (t < 64) {
        uint32_t s = 0;
        #pragma unroll 4
        for (int j = 0; j < 64; j++) s += g_hist[t * 64 + j];
        coarse[t] = s;
    }
    __syncthreads();
    if (t == 0) {
        long long cum = 0;
        int cb = 63;
        for (; cb >= 0; cb--) { cum += coarse[cb]; if (cum >= K) break; }
        if (cb < 0) cb = 0;
        long long above = cum - coarse[cb];   // count in bins >= (cb+1)*64
        int B = cb * 64;
        long long c2 = above;
        for (int b = cb * 64 + 63; b >= cb * 64; b--) {
            c2 += g_hist[b];
            if (c2 >= K) { B = b; break; }
        }
        g_threshBin = B;
    }
}

// K3: compact candidates (bin >= B). Packed key = (key32<<32) | ~idx :
// higher score wins; among equal scores, smaller idx wins (jax tie-break).
__global__ void k_compact(int N) {
    const int B = g_threshBin;
    const int stride = gridDim.x * blockDim.x;
    for (int i = blockIdx.x * blockDim.x + threadIdx.x; i < N; i += stride) {
        uint32_t key = g_keys[i];
        if ((int)(key >> 20) >= B) {
            int p = atomicAdd(&g_count, 1);
            if (p < CAND_CAP)
                g_cand[p] = ((unsigned long long)key << 32) | (uint32_t)(~(uint32_t)i);
        }
    }
}

// K4: exact top-K via 64 successive strict maxima (keys are unique — no
// mutation needed), then gather rows + write idx as floats.
__global__ void k_select(const float4* __restrict__ mat,
                         float* __restrict__ out, int out_size) {
    __shared__ unsigned long long red[256];
    __shared__ uint32_t rows[KSEL];

    int C = g_count;
    if (C > CAND_CAP) C = CAND_CAP;

    unsigned long long prev = 0xFFFFFFFFFFFFFFFFull;
    for (int t = 0; t < KSEL; t++) {
        unsigned long long lm = 0ull;
        for (int j = threadIdx.x; j < C; j += blockDim.x) {
            unsigned long long v = g_cand[j];
            if (v < prev && v > lm) lm = v;
        }
        red[threadIdx.x] = lm;
        __syncthreads();
        for (int s = 128; s; s >>= 1) {
            if (threadIdx.x < s)
                if (red[threadIdx.x + s] > red[threadIdx.x])
                    red[threadIdx.x] = red[threadIdx.x + s];
            __syncthreads();
        }
        prev = red[0];
        if (threadIdx.x == 0)
            rows[t] = ~(uint32_t)(prev & 0xFFFFFFFFull);
        __syncthreads();
    }

    // Gather: 64 rows x 64 float4 = 64 KB
    float4* out4 = (float4*)out;
    for (int e = threadIdx.x; e < KSEL * 64; e += blockDim.x) {
        int r = e >> 6, c = e & 63;
        out4[e] = mat[(size_t)rows[r] * 64 + c];
    }
    // Index output (as float), appended after the rows if space exists
    if (threadIdx.x < KSEL && out_size >= KSEL * 256 + KSEL)
        out[KSEL * 256 + threadIdx.x] = (float)rows[threadIdx.x];
}

extern "C" void kernel_launch(void* const* d_in, const int* in_sizes, int n_in,
                              void* d_out, int out_size) {
    const float* q   = (const float*)d_in[0];   // [256]
    const float* mat = (const float*)d_in[1];   // [500000, 256]
    int D = in_sizes[0];
    int N = in_sizes[1] / D;

    k_zero<<<(NBINS + 255) / 256, 256>>>();
    // 16 blocks/SM worth of warps for full HBM saturation
    k_score<<<2368, 256>>>((const float4*)q, (const float4*)mat, N);
    k_thresh<<<1, 64>>>(KSEL);
    k_compact<<<592, 256>>>(N);
    k_select<<<1, 256>>>((const float4*)mat, (float*)d_out, out_size);
}

// round 2
// speedup vs baseline: 1.3960x; 1.3960x over previous
#include <cuda_runtime.h>
#include <stdint.h>

#define NBINS    4096
#define CAND_CAP 4096
#define MAXN     524288
#define KSEL     64

// Scratch (no allocations allowed; __device__ globals per rules).
// Zero-initialized at module load; k_select re-zeros g_hist/g_count at the
// end of every invocation so each graph replay starts clean.
__device__ uint32_t            g_keys[MAXN];
__device__ uint32_t            g_hist[NBINS];
__device__ int                 g_threshBin;
__device__ int                 g_count;
__device__ unsigned long long  g_cand[CAND_CAP];

// Monotone float -> uint32 mapping (order-preserving incl. negatives)
__device__ __forceinline__ uint32_t f2key(float f) {
    uint32_t u = __float_as_uint(f);
    return (u & 0x80000000u) ? ~u : (u | 0x80000000u);
}

__device__ __forceinline__ float dot4(float4 a, float4 b) {
    return a.x*b.x + a.y*b.y + a.z*b.z + a.w*b.w;
}

// K1: 4 rows per warp iteration -> 8 independent LDG.128 in flight per warp
// (1 KB outstanding) so DRAM latency is covered at ~32 warps/SM.
// Fused shared-mem histogram on top 12 key bits.
__global__ void k_score(const float4* __restrict__ q,
                        const float4* __restrict__ mat, int N) {
    __shared__ uint32_t sh[NBINS];
    for (int i = threadIdx.x; i < NBINS; i += blockDim.x) sh[i] = 0u;
    __syncthreads();

    const int lane   = threadIdx.x & 31;
    const int warp   = (blockIdx.x * blockDim.x + threadIdx.x) >> 5;
    const int nwarps = (gridDim.x * blockDim.x) >> 5;

    const float4 qa = q[lane];
    const float4 qb = q[lane + 32];

    for (int r0 = warp * 4; r0 < N; r0 += nwarps * 4) {
        const float4* p = mat + (size_t)r0 * 64;   // 4 rows x 64 float4
        if (r0 + 3 < N) {
            float4 a0 = p[lane],       b0 = p[lane + 32];
            float4 a1 = p[lane + 64],  b1 = p[lane + 96];
            float4 a2 = p[lane + 128], b2 = p[lane + 160];
            float4 a3 = p[lane + 192], b3 = p[lane + 224];
            float s0 = dot4(a0, qa) + dot4(b0, qb);
            float s1 = dot4(a1, qa) + dot4(b1, qb);
            float s2 = dot4(a2, qa) + dot4(b2, qb);
            float s3 = dot4(a3, qa) + dot4(b3, qb);
            #pragma unroll
            for (int o = 16; o; o >>= 1) {
                s0 += __shfl_xor_sync(0xffffffffu, s0, o);
                s1 += __shfl_xor_sync(0xffffffffu, s1, o);
                s2 += __shfl_xor_sync(0xffffffffu, s2, o);
                s3 += __shfl_xor_sync(0xffffffffu, s3, o);
            }
            if (lane < 4) {
                float s = (lane == 0) ? s0 : (lane == 1) ? s1 : (lane == 2) ? s2 : s3;
                uint32_t key = f2key(s);
                g_keys[r0 + lane] = key;
                atomicAdd(&sh[key >> 20], 1u);
            }
        } else {
            for (int r = r0; r < N; r++) {
                const float4* row = mat + (size_t)r * 64;
                float4 a = row[lane], b = row[lane + 32];
                float s = dot4(a, qa) + dot4(b, qb);
                #pragma unroll
                for (int o = 16; o; o >>= 1) s += __shfl_xor_sync(0xffffffffu, s, o);
                if (lane == 0) {
                    uint32_t key = f2key(s);
                    g_keys[r] = key;
                    atomicAdd(&sh[key >> 20], 1u);
                }
            }
        }
    }
    __syncthreads();
    for (int i = threadIdx.x; i < NBINS; i += blockDim.x) {
        uint32_t c = sh[i];
        if (c) atomicAdd(&g_hist[i], c);
    }
}

// K2: find threshold bin B (bin containing the K-th largest score).
__global__ void k_thresh(int K) {
    __shared__ uint32_t coarse[64];
    int t = threadIdx.x;
    if (t < 64) {
        uint32_t s = 0;
        #pragma unroll 4
        for (int j = 0; j < 64; j++) s += g_hist[t * 64 + j];
        coarse[t] = s;
    }
    __syncthreads();
    if (t == 0) {
        long long cum = 0;
        int cb = 63;
        for (; cb >= 0; cb--) { cum += coarse[cb]; if (cum >= K) break; }
        if (cb < 0) cb = 0;
        long long above = cum - coarse[cb];
        int B = cb * 64;
        long long c2 = above;
        for (int b = cb * 64 + 63; b >= cb * 64; b--) {
            c2 += g_hist[b];
            if (c2 >= K) { B = b; break; }
        }
        g_threshBin = B;
    }
}

// K3: compact candidates (bin >= B), uint4-vectorized key reads.
// Packed key = (key32<<32) | ~idx : higher score first; ties -> smaller idx.
__global__ void k_compact(int N4) {
    const int B = g_threshBin;
    const int stride = gridDim.x * blockDim.x;
    const uint4* keys4 = (const uint4*)g_keys;
    for (int i = blockIdx.x * blockDim.x + threadIdx.x; i < N4; i += stride) {
        uint4 k4 = keys4[i];
        uint32_t base = (uint32_t)i * 4u;
        #pragma unroll
        for (int j = 0; j < 4; j++) {
            uint32_t key = (j == 0) ? k4.x : (j == 1) ? k4.y : (j == 2) ? k4.z : k4.w;
            if ((int)(key >> 20) >= B) {
                int p = atomicAdd(&g_count, 1);
                if (p < CAND_CAP)
                    g_cand[p] = ((unsigned long long)key << 32)
                              | (uint32_t)(~(base + (uint32_t)j));
            }
        }
    }
}

// K4: exact top-K by rank computation (keys unique -> ranks unique),
// then gather rows + write idx as floats. Also resets g_hist/g_count
// so the next graph replay starts from clean state.
__global__ void k_select(const float4* __restrict__ mat,
                         float* __restrict__ out, int out_size) {
    __shared__ unsigned long long cv[CAND_CAP];
    __shared__ uint32_t rows[KSEL];

    int C = g_count;
    if (C > CAND_CAP) C = CAND_CAP;

    for (int j = threadIdx.x; j < C; j += blockDim.x) cv[j] = g_cand[j];
    __syncthreads();

    // rank(v) = #{v' > v}; rank < KSEL -> selected, position = rank
    for (int j = threadIdx.x; j < C; j += blockDim.x) {
        unsigned long long v = cv[j];
        int rank = 0;
        for (int i = 0; i < C; i++) rank += (cv[i] > v);
        if (rank < KSEL) rows[rank] = ~(uint32_t)(v & 0xFFFFFFFFull);
    }
    __syncthreads();

    // Gather: 64 rows x 64 float4 = 64 KB
    float4* out4 = (float4*)out;
    for (int e = threadIdx.x; e < KSEL * 64; e += blockDim.x) {
        int r = e >> 6, c = e & 63;
        out4[e] = mat[(size_t)rows[r] * 64 + c];
    }
    // Index output (as float), appended after the rows
    if (threadIdx.x < KSEL && out_size >= KSEL * 256 + KSEL)
        out[KSEL * 256 + threadIdx.x] = (float)rows[threadIdx.x];

    // Reset scratch for next replay
    for (int i = threadIdx.x; i < NBINS; i += blockDim.x) g_hist[i] = 0u;
    if (threadIdx.x == 0) g_count = 0;
}

extern "C" void kernel_launch(void* const* d_in, const int* in_sizes, int n_in,
                              void* d_out, int out_size) {
    const float* q   = (const float*)d_in[0];   // [256]
    const float* mat = (const float*)d_in[1];   // [500000, 256]
    int D = in_sizes[0];
    int N = in_sizes[1] / D;

    // ~4 blocks/SM resident (reg-limited), grid-stride persistent
    k_score<<<592, 256>>>((const float4*)q, (const float4*)mat, N);
    k_thresh<<<1, 64>>>(KSEL);
    k_compact<<<592, 256>>>(N / 4);
    k_select<<<1, 256>>>((const float4*)mat, (float*)d_out, out_size);
}